// round 1
// baseline (speedup 1.0000x reference)
#include <cuda_runtime.h>

#define NB   4
#define CIN  32
#define CC   64
#define NPTS 32768      // points per batch
#define V3   32768      // 32^3 voxels
#define NG   8
#define EPS  1e-5f

// ---------------- scratch (device globals; no allocation allowed) ----------
__device__ __align__(16) float g_buf1[NB * CC * NPTS];   // y / out_pre
__device__ __align__(16) float g_buf2[NB * CC * V3];     // vox_sum/vox0 ; conv2 out
__device__ __align__(16) float g_buf3[NB * CC * V3];     // conv1 out ; voxT (b,v,c)
__device__ int   g_cnt[NB * V3];
__device__ float g_bias[NB * CC];
__device__ float g_mu[NB * NG];
__device__ float g_rs[NB * NG];

__device__ __forceinline__ float siluf(float x) { return x / (1.f + __expf(-x)); }

// ---------------- K1: time bias  bias[b,o] = t_emb[b,:] @ w_time[o,:] + b_time[o]
__global__ void k_bias(const float* __restrict__ t_emb,
                       const float* __restrict__ w_time,
                       const float* __restrict__ b_time) {
    __shared__ float te[256];
    int b = blockIdx.x, o = threadIdx.x;
    for (int i = o; i < 256; i += 64) te[i] = t_emb[b * 256 + i];
    __syncthreads();
    float s = b_time[o];
    #pragma unroll 8
    for (int t = 0; t < 256; t++) s += te[t] * w_time[o * 256 + t];
    g_bias[b * CC + o] = s;
}

// ---------------- K2: y[b,o,n] = sum_c w_in[o,c] * feats[b,c,n]
__global__ void __launch_bounds__(128) k_pw_in(const float* __restrict__ feats,
                                               const float* __restrict__ w) {
    __shared__ float4 sw[CIN * 16];                 // transposed [c][o/4]
    for (int i = threadIdx.x; i < CIN * CC; i += 128) {
        int o = i >> 5, c = i & 31;
        ((float*)sw)[c * CC + o] = w[i];
    }
    __syncthreads();
    int p = blockIdx.x * 128 + threadIdx.x;         // 0 .. B*N-1
    int b = p >> 15, n = p & 32767;
    float acc[CC];
    #pragma unroll
    for (int o = 0; o < CC; o++) acc[o] = 0.f;
    #pragma unroll 4
    for (int c = 0; c < CIN; c++) {
        float x = feats[((b * CIN + c) << 15) + n];
        const float4* wr = sw + c * 16;
        #pragma unroll
        for (int q = 0; q < 16; q++) {
            float4 ww = wr[q];
            acc[q * 4 + 0] += x * ww.x; acc[q * 4 + 1] += x * ww.y;
            acc[q * 4 + 2] += x * ww.z; acc[q * 4 + 3] += x * ww.w;
        }
    }
    #pragma unroll
    for (int o = 0; o < CC; o++) g_buf1[((b * CC + o) << 15) + n] = acc[o];
}

// ---------------- GN stats: per (b,g) mean & rstd over contiguous 262144 floats
__global__ void k_stats(const float* __restrict__ buf) {
    __shared__ float ssum[256], ssq[256];
    int bg = blockIdx.x;                            // 0..31
    const float4* p = (const float4*)(buf + (size_t)bg * 262144);
    float s = 0.f, q = 0.f;
    for (int i = threadIdx.x; i < 65536; i += 256) {
        float4 v = p[i];
        s += v.x + v.y + v.z + v.w;
        q += v.x * v.x + v.y * v.y + v.z * v.z + v.w * v.w;
    }
    ssum[threadIdx.x] = s; ssq[threadIdx.x] = q;
    __syncthreads();
    for (int st = 128; st > 0; st >>= 1) {
        if (threadIdx.x < st) {
            ssum[threadIdx.x] += ssum[threadIdx.x + st];
            ssq[threadIdx.x]  += ssq[threadIdx.x + st];
        }
        __syncthreads();
    }
    if (threadIdx.x == 0) {
        float mean = ssum[0] * (1.f / 262144.f);
        float var  = ssq[0] * (1.f / 262144.f) - mean * mean;
        g_mu[bg] = mean;
        g_rs[bg] = rsqrtf(var + EPS);
    }
}

// ---------------- zero vox accumulators
__global__ void k_zero() {
    int idx = blockIdx.x * 256 + threadIdx.x;       // covers 8388608
    g_buf2[idx] = 0.f;
    if (idx < NB * V3) g_cnt[idx] = 0;
}

// ---------------- K4: GN1 + SiLU + bias, scatter-add into voxel grid
__global__ void __launch_bounds__(128) k_scatter(const float* __restrict__ coords,
                                                 const float* __restrict__ gg,
                                                 const float* __restrict__ gb) {
    int p = blockIdx.x * 128 + threadIdx.x;
    int b = p >> 15, n = p & 32767;
    float cx = coords[p * 3 + 0] * 31.f;
    float cy = coords[p * 3 + 1] * 31.f;
    float cz = coords[p * 3 + 2] * 31.f;
    int ix = min(max(__float2int_rd(cx), 0), 31);
    int iy = min(max(__float2int_rd(cy), 0), 31);
    int iz = min(max(__float2int_rd(cz), 0), 31);
    int flat = (ix << 10) + (iy << 5) + iz;
    atomicAdd(&g_cnt[(b << 15) + flat], 1);
    #pragma unroll 4
    for (int c = 0; c < CC; c++) {
        int bg = b * NG + (c >> 3);
        float x = g_buf1[((b * CC + c) << 15) + n];
        x = (x - g_mu[bg]) * g_rs[bg] * gg[c] + gb[c];
        x = siluf(x) + g_bias[b * CC + c];
        atomicAdd(&g_buf2[((b * CC + c) << 15) + flat], x);
    }
}

// ---------------- K5: vox = sum / max(cnt,1) + bias
__global__ void k_voxfin() {
    int idx = blockIdx.x * 256 + threadIdx.x;       // 8388608
    int v = idx & 32767, bc = idx >> 15;
    int b = bc >> 6;
    int cnt = g_cnt[(b << 15) + v];
    float s = g_buf2[idx];
    g_buf2[idx] = s / (float)max(cnt, 1) + g_bias[bc];
}

// ---------------- conv3d 3x3x3, 64->64 ch, SAME pad
// block: 8^3 spatial tile x 16 out-ch; 128 threads; 4 voxels x 16 oc per thread
__global__ void __launch_bounds__(128) k_conv(const float* __restrict__ in,
                                              const float* __restrict__ w,
                                              float* __restrict__ out) {
    __shared__ float s_in[8 * 1000];                // 8 ci x 10x10x10 halo
    __shared__ float s_w[16 * 216];                 // [oo][ci*27+t]
    int tile = blockIdx.x;                          // 0..63
    int txw = (tile & 3) << 3, tyh = ((tile >> 2) & 3) << 3, tzd = ((tile >> 4) & 3) << 3;
    int og = blockIdx.y, b = blockIdx.z;
    int tid = threadIdx.x;

    int sb[4], gob[4];
    #pragma unroll
    for (int k = 0; k < 4; k++) {
        int v = tid + (k << 7);
        int ld = v >> 6, lh = (v >> 3) & 7, lw = v & 7;
        sb[k]  = ld * 100 + lh * 10 + lw;
        gob[k] = ((b * CC + og * 16) << 15) + ((tzd + ld) << 10) + ((tyh + lh) << 5) + (txw + lw);
    }
    float acc[4][16];
    #pragma unroll
    for (int k = 0; k < 4; k++)
        #pragma unroll
        for (int o = 0; o < 16; o++) acc[k][o] = 0.f;

    const float* inb = in + ((b * CC) << 15);
    for (int chunk = 0; chunk < 8; chunk++) {
        __syncthreads();
        int ci0 = chunk * 8;
        for (int i = tid; i < 8000; i += 128) {
            int ci = i / 1000, r = i - ci * 1000;
            int dz = r / 100; int rr = r - dz * 100;
            int dy = rr / 10; int dx = rr - dy * 10;
            int gd = tzd + dz - 1, gh = tyh + dy - 1, gw = txw + dx - 1;
            float vv = 0.f;
            if (((unsigned)gd < 32u) && ((unsigned)gh < 32u) && ((unsigned)gw < 32u))
                vv = inb[((ci0 + ci) << 15) + (gd << 10) + (gh << 5) + gw];
            s_in[i] = vv;
        }
        for (int i = tid; i < 3456; i += 128) {
            int oo = i / 216, r = i - oo * 216;     // r = ci*27 + t
            s_w[i] = w[((og * 16 + oo) * CC + ci0) * 27 + r];
        }
        __syncthreads();
        for (int ci = 0; ci < 8; ci++) {
            const float* sI = s_in + ci * 1000;
            const float* sW = s_w + ci * 27;
            for (int kd = 0; kd < 3; kd++) {
                const float* sId = sI + kd * 100;
                const float* sWd = sW + kd * 9;
                #pragma unroll
                for (int kh = 0; kh < 3; kh++) {
                    #pragma unroll
                    for (int kw = 0; kw < 3; kw++) {
                        int toff = kh * 10 + kw;
                        int t = kh * 3 + kw;
                        float x0 = sId[sb[0] + toff], x1 = sId[sb[1] + toff];
                        float x2 = sId[sb[2] + toff], x3 = sId[sb[3] + toff];
                        #pragma unroll
                        for (int oo = 0; oo < 16; oo++) {
                            float ww = sWd[oo * 216 + t];
                            acc[0][oo] += x0 * ww; acc[1][oo] += x1 * ww;
                            acc[2][oo] += x2 * ww; acc[3][oo] += x3 * ww;
                        }
                    }
                }
            }
        }
    }
    #pragma unroll
    for (int k = 0; k < 4; k++)
        #pragma unroll
        for (int oo = 0; oo < 16; oo++)
            out[gob[k] + (oo << 15)] = acc[k][oo];
}

// ---------------- GN + SiLU in place
__global__ void k_gnsilu(float* __restrict__ buf,
                         const float* __restrict__ gg, const float* __restrict__ gb) {
    int idx = blockIdx.x * 256 + threadIdx.x;
    int c = (idx >> 15) & 63, b = idx >> 21;
    int bg = b * NG + (c >> 3);
    float x = buf[idx];
    x = (x - g_mu[bg]) * g_rs[bg] * gg[c] + gb[c];
    buf[idx] = siluf(x);
}

// ---------------- GN3 + SiLU + transpose (b,c,v) -> (b,v,c) into g_buf3
__global__ void k_gnsilu_tr(const float* __restrict__ gg, const float* __restrict__ gb) {
    __shared__ float s[64 * 33];
    int b = blockIdx.y;
    int v0 = blockIdx.x << 5;
    int tid = threadIdx.x;
    #pragma unroll
    for (int k = 0; k < 8; k++) {
        int i = tid + (k << 8);
        int c = i >> 5, v = i & 31;
        float x = g_buf2[((b * CC + c) << 15) + v0 + v];
        int bg = b * NG + (c >> 3);
        x = (x - g_mu[bg]) * g_rs[bg] * gg[c] + gb[c];
        s[c * 33 + v] = siluf(x);
    }
    __syncthreads();
    #pragma unroll
    for (int k = 0; k < 8; k++) {
        int i = tid + (k << 8);
        int v = i >> 6, c = i & 63;
        g_buf3[(((b << 15) + v0 + v) << 6) + c] = s[c * 33 + v];
    }
}

// ---------------- devoxelize (trilinear) + fuse GEMM -> out_pre in g_buf1
__global__ void __launch_bounds__(128) k_devox(const float* __restrict__ coords,
                                               const float* __restrict__ wfuse) {
    __shared__ float4 swf[64 * 16];                 // transposed [c][o/4]
    for (int i = threadIdx.x; i < CC * CC; i += 128) {
        int o = i >> 6, c = i & 63;
        ((float*)swf)[(c << 6) + o] = wfuse[i];
    }
    __syncthreads();
    int p = blockIdx.x * 128 + threadIdx.x;
    int b = p >> 15, n = p & 32767;
    float cx = coords[p * 3 + 0] * 31.f;
    float cy = coords[p * 3 + 1] * 31.f;
    float cz = coords[p * 3 + 2] * 31.f;
    float fx = cx - floorf(cx), fy = cy - floorf(cy), fz = cz - floorf(cz);
    int x0 = min(max(__float2int_rd(cx), 0), 31); int x1 = min(x0 + 1, 31);
    int y0 = min(max(__float2int_rd(cy), 0), 31); int y1 = min(y0 + 1, 31);
    int z0 = min(max(__float2int_rd(cz), 0), 31); int z1 = min(z0 + 1, 31);
    float wx0 = 1.f - fx, wy0 = 1.f - fy, wz0 = 1.f - fz;

    const float4* base[8];
    float wk[8];
    int k = 0;
    #pragma unroll
    for (int dx = 0; dx < 2; dx++)
        #pragma unroll
        for (int dy = 0; dy < 2; dy++)
            #pragma unroll
            for (int dz = 0; dz < 2; dz++) {
                int X = dx ? x1 : x0, Y = dy ? y1 : y0, Z = dz ? z1 : z0;
                wk[k] = (dx ? fx : wx0) * (dy ? fy : wy0) * (dz ? fz : wz0);
                base[k] = (const float4*)(g_buf3 + (((b << 15) + ((X << 10) + (Y << 5) + Z)) << 6));
                k++;
            }

    float acc[CC];
    #pragma unroll
    for (int o = 0; o < CC; o++) acc[o] = 0.f;

    #pragma unroll
    for (int c4 = 0; c4 < 16; c4++) {
        float r[32];
        #pragma unroll
        for (int kk = 0; kk < 8; kk++) {
            float4 v = __ldg(base[kk] + c4);
            r[kk * 4 + 0] = v.x; r[kk * 4 + 1] = v.y; r[kk * 4 + 2] = v.z; r[kk * 4 + 3] = v.w;
        }
        #pragma unroll
        for (int j = 0; j < 4; j++) {
            float d = r[j] * wk[0] + r[4 + j] * wk[1] + r[8 + j] * wk[2] + r[12 + j] * wk[3]
                    + r[16 + j] * wk[4] + r[20 + j] * wk[5] + r[24 + j] * wk[6] + r[28 + j] * wk[7];
            const float4* wr = swf + ((c4 * 4 + j) << 4);
            #pragma unroll
            for (int q = 0; q < 16; q++) {
                float4 ww = wr[q];
                acc[q * 4 + 0] += d * ww.x; acc[q * 4 + 1] += d * ww.y;
                acc[q * 4 + 2] += d * ww.z; acc[q * 4 + 3] += d * ww.w;
            }
        }
    }
    #pragma unroll
    for (int o = 0; o < CC; o++) g_buf1[((b * CC + o) << 15) + n] = acc[o];
}

// ---------------- final: out = silu(GN4(out_pre)) + w_skip @ feats
__global__ void __launch_bounds__(128) k_final(const float* __restrict__ feats,
                                               const float* __restrict__ wskip,
                                               const float* __restrict__ gg,
                                               const float* __restrict__ gb,
                                               float* __restrict__ out) {
    __shared__ float4 sw[CIN * 16];
    __shared__ float sg[64], sb2[64];
    for (int i = threadIdx.x; i < CIN * CC; i += 128) {
        int o = i >> 5, c = i & 31;
        ((float*)sw)[c * CC + o] = wskip[i];
    }
    if (threadIdx.x < 64) { sg[threadIdx.x] = gg[threadIdx.x]; sb2[threadIdx.x] = gb[threadIdx.x]; }
    __syncthreads();
    int p = blockIdx.x * 128 + threadIdx.x;
    int b = p >> 15, n = p & 32767;
    float acc[CC];
    #pragma unroll
    for (int o = 0; o < CC; o++) acc[o] = 0.f;
    #pragma unroll 4
    for (int c = 0; c < CIN; c++) {
        float x = feats[((b * CIN + c) << 15) + n];
        const float4* wr = sw + c * 16;
        #pragma unroll
        for (int q = 0; q < 16; q++) {
            float4 ww = wr[q];
            acc[q * 4 + 0] += x * ww.x; acc[q * 4 + 1] += x * ww.y;
            acc[q * 4 + 2] += x * ww.z; acc[q * 4 + 3] += x * ww.w;
        }
    }
    #pragma unroll
    for (int o = 0; o < CC; o++) {
        int bg = b * NG + (o >> 3);
        float v = g_buf1[((b * CC + o) << 15) + n];
        v = (v - g_mu[bg]) * g_rs[bg] * sg[o] + sb2[o];
        out[((b * CC + o) << 15) + n] = siluf(v) + acc[o];
    }
}

// ---------------------------------------------------------------------------
extern "C" void kernel_launch(void* const* d_in, const int* in_sizes, int n_in,
                              void* d_out, int out_size) {
    const float* feats  = (const float*)d_in[0];
    const float* coords = (const float*)d_in[1];
    const float* t_emb  = (const float*)d_in[2];
    const float* w_in   = (const float*)d_in[3];
    const float* gn1_g  = (const float*)d_in[4];
    const float* gn1_b  = (const float*)d_in[5];
    const float* w_time = (const float*)d_in[6];
    const float* b_time = (const float*)d_in[7];
    const float* w_vox1 = (const float*)d_in[8];
    const float* gn2_g  = (const float*)d_in[9];
    const float* gn2_b  = (const float*)d_in[10];
    const float* w_vox2 = (const float*)d_in[11];
    const float* gn3_g  = (const float*)d_in[12];
    const float* gn3_b  = (const float*)d_in[13];
    const float* w_fuse = (const float*)d_in[14];
    const float* gn4_g  = (const float*)d_in[15];
    const float* gn4_b  = (const float*)d_in[16];
    const float* w_skip = (const float*)d_in[17];
    float* out = (float*)d_out;

    float *b1, *b2, *b3;
    cudaGetSymbolAddress((void**)&b1, g_buf1);
    cudaGetSymbolAddress((void**)&b2, g_buf2);
    cudaGetSymbolAddress((void**)&b3, g_buf3);

    k_bias<<<NB, 64>>>(t_emb, w_time, b_time);
    k_pw_in<<<1024, 128>>>(feats, w_in);
    k_stats<<<32, 256>>>(b1);                          // GN1 stats
    k_zero<<<32768, 256>>>();
    k_scatter<<<1024, 128>>>(coords, gn1_g, gn1_b);    // GN1+SiLU+bias, scatter
    k_voxfin<<<32768, 256>>>();                        // mean + bias -> vox0 (b2)
    k_conv<<<dim3(64, 4, 4), 128>>>(b2, w_vox1, b3);   // conv1 -> b3
    k_stats<<<32, 256>>>(b3);                          // GN2 stats
    k_gnsilu<<<32768, 256>>>(b3, gn2_g, gn2_b);        // GN2+SiLU in place
    k_conv<<<dim3(64, 4, 4), 128>>>(b3, w_vox2, b2);   // conv2 -> b2
    k_stats<<<32, 256>>>(b2);                          // GN3 stats
    k_gnsilu_tr<<<dim3(1024, NB), 256>>>(gn3_g, gn3_b);// GN3+SiLU + transpose -> b3 (b,v,c)
    k_devox<<<1024, 128>>>(coords, w_fuse);            // trilinear + fuse -> b1
    k_stats<<<32, 256>>>(b1);                          // GN4 stats
    k_final<<<1024, 128>>>(feats, w_skip, gn4_g, gn4_b, out);
}